// round 14
// baseline (speedup 1.0000x reference)
#include <cuda_runtime.h>
#include <cuda_bf16.h>
#include <math.h>
#include <stdint.h>

#define B    4
#define C    64
#define H    128
#define W    128
#define COUT 64
#define KK   18
#define CK   576
#define HW   16384
#define PW   131              // padded width/height (y,x in -1..129)
#define PPX  (PW * PW)        // 17161 padded pixels per image
#define NTILES 512            // one tile = one image row (128 px)
#define RPAD 144              // smem row pitch in bytes (72 bf16)

// Scratch (device globals — no runtime allocation allowed)
__device__ float g_xp[B * PPX * C];          // zero-padded NHWC x
__device__ float g_off[B * HW * KK];         // offsets [b][y][x][18]
__device__ __nv_bfloat16 g_Bhi[9 * 64 * 64]; // w_d [tap][o][c] bf16 hi
__device__ __nv_bfloat16 g_Blo[9 * 64 * 64]; // w_d [tap][o][c] bf16 lo
__device__ __nv_bfloat16 g_Phi[9 * 32 * 64]; // w_p [tap][kk(pad32)][c] hi
__device__ __nv_bfloat16 g_Plo[9 * 32 * 64]; // w_p [tap][kk(pad32)][c] lo

// ---------------- warp-MMA helpers (baseline PTX, sm_80+) ----------------
__device__ __forceinline__ uint32_t smem_u32(const void* p) {
    uint32_t a;
    asm("{ .reg .u64 t; cvta.to.shared.u64 t, %1; cvt.u32.u64 %0, t; }"
        : "=r"(a) : "l"(p));
    return a;
}
__device__ __forceinline__ void ldsm_x4(uint32_t* r, uint32_t addr) {
    asm volatile("ldmatrix.sync.aligned.m8n8.x4.shared.b16 {%0,%1,%2,%3}, [%4];"
                 : "=r"(r[0]), "=r"(r[1]), "=r"(r[2]), "=r"(r[3]) : "r"(addr));
}
__device__ __forceinline__ void ldsm_x2(uint32_t* r, uint32_t addr) {
    asm volatile("ldmatrix.sync.aligned.m8n8.x2.shared.b16 {%0,%1}, [%2];"
                 : "=r"(r[0]), "=r"(r[1]) : "r"(addr));
}
__device__ __forceinline__ void mma_bf16(float* c, const uint32_t* a,
                                         const uint32_t* b) {
    asm volatile(
        "mma.sync.aligned.m16n8k16.row.col.f32.bf16.bf16.f32 "
        "{%0,%1,%2,%3}, {%4,%5,%6,%7}, {%8,%9}, {%0,%1,%2,%3};"
        : "+f"(c[0]), "+f"(c[1]), "+f"(c[2]), "+f"(c[3])
        : "r"(a[0]), "r"(a[1]), "r"(a[2]), "r"(a[3]), "r"(b[0]), "r"(b[1]));
}
// split two f32 into packed bf16 hi + packed bf16 lo residual
__device__ __forceinline__ void split2(float s0, float s1,
                                       unsigned& hi, unsigned& lo) {
    unsigned h;
    asm("cvt.rn.bf16x2.f32 %0, %1, %2;" : "=r"(h) : "f"(s1), "f"(s0));
    float f0 = __uint_as_float(h << 16);
    float f1 = __uint_as_float(h & 0xffff0000u);
    unsigned l;
    asm("cvt.rn.bf16x2.f32 %0, %1, %2;" : "=r"(l) : "f"(s1 - f1), "f"(s0 - f0));
    hi = h; lo = l;
}

// ---------------------------------------------------------------------------
// Kernel 0: zero the padded border of g_xp (777 border px per image)
// ---------------------------------------------------------------------------
__global__ void k_zero() {
    int i = blockIdx.x * 256 + threadIdx.x;   // 777*4*64 = 198912 items
    int c = i & 63;
    int t = i >> 6;
    int p = t % 777;
    int b = t / 777;
    int ys, xs;
    if (p < 393) {
        int r = p / 131;
        ys = (r == 0) ? 0 : 128 + r;
        xs = p % 131;
    } else {
        int q = p - 393;
        ys = q / 3 + 1;
        int cc = q % 3;
        xs = (cc == 0) ? 0 : 128 + cc;
    }
    g_xp[((long)b * PPX + ys * PW + xs) * C + c] = 0.f;
}

// ---------------------------------------------------------------------------
// Kernel 1: transpose x (B,C,H,W) -> padded NHWC interior
// ---------------------------------------------------------------------------
__global__ void k_transpose_x(const float* __restrict__ x) {
    __shared__ float tile[32][33];
    int b   = blockIdx.z;
    int c0  = blockIdx.y * 32;
    int hw0 = blockIdx.x * 32;
    int tx = threadIdx.x, ty = threadIdx.y;
#pragma unroll
    for (int j = 0; j < 4; j++)
        tile[ty + j * 8][tx] = x[(b * C + c0 + ty + j * 8) * HW + hw0 + tx];
    __syncthreads();
#pragma unroll
    for (int j = 0; j < 4; j++) {
        int hw = hw0 + ty + j * 8;
        int yy = hw >> 7, xx = hw & 127;
        g_xp[((long)b * PPX + (yy + 1) * PW + xx + 1) * C + c0 + tx]
            = tile[tx][ty + j * 8];
    }
}

// ---------------------------------------------------------------------------
// Kernel 2: weight prep — bf16 hi/lo split for both w_d and w_p
// ---------------------------------------------------------------------------
__global__ void k_wprep(const float* __restrict__ wd,
                        const float* __restrict__ wp) {
    int i = blockIdx.x * 256 + threadIdx.x;
    if (i < 9 * 64 * 64) {
        int c = i & 63, o = (i >> 6) & 63, k = i >> 12;
        float v = wd[o * CK + c * 9 + k];
        __nv_bfloat16 h = __float2bfloat16(v);
        g_Bhi[k * 4096 + o * 64 + c] = h;
        g_Blo[k * 4096 + o * 64 + c] = __float2bfloat16(v - __bfloat162float(h));
    } else if (i < 9 * 64 * 64 + 9 * 32 * 64) {
        int j = i - 9 * 64 * 64;
        int c = j & 63, kk = (j >> 6) & 31, k = j >> 11;
        float v = (kk < 18) ? wp[kk * CK + c * 9 + k] : 0.f;
        __nv_bfloat16 h = __float2bfloat16(v);
        g_Phi[k * 2048 + kk * 64 + c] = h;
        g_Plo[k * 2048 + kk * 64 + c] = __float2bfloat16(v - __bfloat162float(h));
    }
}

// ---------------------------------------------------------------------------
// Kernel 3: offset conv as bf16-split HMMA GEMM, row-shift A sharing,
// n=24 warp layout: warp wid -> m = wid*16 (1 m-frag), n = 0..23 (3 n-frags).
// ---------------------------------------------------------------------------
__global__ void __launch_bounds__(256) k_off2(const float* __restrict__ bp) {
    extern __shared__ char smem[];
    char* sAhi = smem;
    char* sAlo = smem + 18720;
    char* sP   = smem + 37440;          // [tap][hi 4608 | lo 4608]
    uint32_t sb  = smem_u32(smem);
    uint32_t AHI = sb, ALO = sb + 18720, PB = sb + 37440;

    int tid  = threadIdx.x;
    int lane = tid & 31;
    int wid  = tid >> 5;
    int tile = blockIdx.x;
    int b    = tile >> 7;
    int y    = tile & 127;

    int c4  = (tid & 15) * 4;
    int pxg = tid >> 4;
    const float* xbase = g_xp + (long)b * PPX * C + c4;

    int wm = wid * 16;
    float acc[3][4];
#pragma unroll
    for (int j = 0; j < 3; j++)
#pragma unroll
        for (int q = 0; q < 4; q++) acc[j][q] = 0.f;

#pragma unroll 1
    for (int ky = 0; ky < 3; ky++) {
        const float* rowp = xbase + (long)((y + ky) * PW) * C;
        // ---- build Awide: 130 stored-px x 64 ch (hi/lo split)
#pragma unroll
        for (int i = 0; i < 8; i++) {
            int j = pxg + 16 * i;
            float4 v = *(const float4*)(rowp + j * C);
            unsigned h0, l0, h1, l1;
            split2(v.x, v.y, h0, l0);
            split2(v.z, v.w, h1, l1);
            *(uint2*)(sAhi + j * RPAD + c4 * 2) = make_uint2(h0, h1);
            *(uint2*)(sAlo + j * RPAD + c4 * 2) = make_uint2(l0, l1);
        }
        if (tid < 32) {                  // px 128, 129
            int j = 128 + (tid >> 4);
            float4 v = *(const float4*)(rowp + j * C);
            unsigned h0, l0, h1, l1;
            split2(v.x, v.y, h0, l0);
            split2(v.z, v.w, h1, l1);
            *(uint2*)(sAhi + j * RPAD + c4 * 2) = make_uint2(h0, h1);
            *(uint2*)(sAlo + j * RPAD + c4 * 2) = make_uint2(l0, l1);
        }
        // ---- preload this ky's 3 weight tiles (hi+lo)
#pragma unroll
        for (int j = 0; j < 6; j++) {
            int idx  = tid + j * 256;
            int tap  = idx >> 9;
            int r    = idx & 511;
            int half = r >> 8;
            int e    = r & 255;
            int o    = e >> 3, kc = e & 7;
            const uint4* src = half
                ? (const uint4*)(g_Plo + (ky * 3 + tap) * 2048)
                : (const uint4*)(g_Phi + (ky * 3 + tap) * 2048);
            *(uint4*)(sP + tap * 9216 + half * 4608 + o * RPAD + kc * 16)
                = src[e];
        }
        __syncthreads();

        // ---- 3 taps from the shared Awide (base shifted by kx*RPAD)
#pragma unroll
        for (int kx = 0; kx < 3; kx++) {
            uint32_t Abase = (uint32_t)(kx * RPAD);
            uint32_t PHI = PB + kx * 9216, PLO = PHI + 4608;
#pragma unroll
            for (int ks = 0; ks < 4; ks++) {
                int kcol = ks * 16;
                uint32_t ahi[4], alo[4], bhi[3][2], blo[3][2];
                uint32_t ar = Abase
                    + (uint32_t)(wm + (lane & 15)) * RPAD
                    + (uint32_t)(kcol + (lane >> 4) * 8) * 2;
                ldsm_x4(ahi, AHI + ar);
                ldsm_x4(alo, ALO + ar);
#pragma unroll
                for (int nf = 0; nf < 3; nf++) {
                    uint32_t br = (uint32_t)(nf * 8 + (lane & 7)) * RPAD
                                + (uint32_t)(kcol + ((lane >> 3) & 1) * 8) * 2;
                    ldsm_x2(bhi[nf], PHI + br);
                    ldsm_x2(blo[nf], PLO + br);
                }
#pragma unroll
                for (int nf = 0; nf < 3; nf++) {
                    mma_bf16(acc[nf], ahi, bhi[nf]);
                    mma_bf16(acc[nf], ahi, blo[nf]);
                    mma_bf16(acc[nf], alo, bhi[nf]);
                }
            }
        }
        __syncthreads();
    }

    float* Cst = (float*)smem;
#pragma unroll
    for (int nf = 0; nf < 3; nf++) {
        int row0 = wm + (lane >> 2);
        int col0 = nf * 8 + (lane & 3) * 2;
        if (col0 < 18) {
            Cst[(row0    ) * 20 + col0] = acc[nf][0];
            Cst[(row0 + 8) * 20 + col0] = acc[nf][2];
        }
        if (col0 + 1 < 18) {
            Cst[(row0    ) * 20 + col0 + 1] = acc[nf][1];
            Cst[(row0 + 8) * 20 + col0 + 1] = acc[nf][3];
        }
    }
    __syncthreads();
    {
        int px = tid >> 1;
        int g  = tid & 1;
        float* op = g_off + (long)(b * HW + y * W + px) * KK;
#pragma unroll
        for (int j = 0; j < 9; j++) {
            int kk = g * 9 + j;
            op[kk] = Cst[px * 20 + kk] + bp[kk];
        }
    }
}

// ---------------------------------------------------------------------------
// Kernel 4: fused gather + bf16-split warp-MMA GEMM.
// Offsets for the row preloaded into smem (kills 16x-redundant scalar LDGs).
// smem: A 36864 | B 18432 @36864 | OFFS 9216 @55296 = 64512 B.
// ---------------------------------------------------------------------------
__global__ void __launch_bounds__(256, 2) k_fused(float* __restrict__ out) {
    extern __shared__ char smem[];
    char* sAhi = smem;
    char* sAlo = smem + 18432;
    char* sBhi = smem + 36864;
    char* sBlo = smem + 46080;
    float* OFFS = (float*)(smem + 55296);   // [128 px][18]
    uint32_t sb  = smem_u32(smem);
    uint32_t AHI = sb, ALO = sb + 18432, BHI = sb + 36864, BLO = sb + 46080;

    int tid  = threadIdx.x;
    int lane = tid & 31;
    int wid  = tid >> 5;
    int tile = blockIdx.x;
    int b    = tile >> 7;
    int y    = tile & 127;

    int c4  = (tid & 15) * 4;
    int pxg = tid >> 4;
    const float* xbase = g_xp + (long)b * PPX * C + c4;

    // preload this row's offsets (2304 contiguous floats)
    {
        const float* offrow = g_off + (long)(b * HW + y * W) * KK;
#pragma unroll
        for (int j = 0; j < 9; j++)
            OFFS[tid + j * 256] = offrow[tid + j * 256];
    }
    __syncthreads();

    int wm = (wid & 3) * 32;
    int wn = (wid >> 2) * 32;
    float acc[2][4][4];
#pragma unroll
    for (int i = 0; i < 2; i++)
#pragma unroll
        for (int j = 0; j < 4; j++)
#pragma unroll
            for (int q = 0; q < 4; q++) acc[i][j][q] = 0.f;

#pragma unroll 1
    for (int k = 0; k < 9; k++) {
        int ky = k / 3 - 1, kx = k % 3 - 1;
        // ---- gather tap k -> A_hi/A_lo (maskless padded bilinear)
#pragma unroll
        for (int i = 0; i < 8; i++) {
            int px = pxg + 16 * i;
            const float* op = OFFS + px * KK;
            float py  = op[2*k]     + (float)(y  + ky);
            float pxx = op[2*k + 1] + (float)(px + kx);
            py  = fminf(fmaxf(py,  -1.f), 128.f);
            pxx = fminf(fmaxf(pxx, -1.f), 128.f);
            float fy = floorf(py), fx = floorf(pxx);
            float wy = py - fy,    wx = pxx - fx;
            int iy = (int)fy + 1;
            int ix = (int)fx + 1;
            int base = (iy * PW + ix) << 6;
            float4 a00 = *(const float4*)(xbase + base);
            float4 a01 = *(const float4*)(xbase + base + 64);
            float4 a10 = *(const float4*)(xbase + base + PW * 64);
            float4 a11 = *(const float4*)(xbase + base + (PW + 1) * 64);
            float w00 = (1.f - wy) * (1.f - wx);
            float w01 = (1.f - wy) * wx;
            float w10 = wy * (1.f - wx);
            float w11 = wy * wx;
            float s0 = w00*a00.x + w01*a01.x + w10*a10.x + w11*a11.x;
            float s1 = w00*a00.y + w01*a01.y + w10*a10.y + w11*a11.y;
            float s2 = w00*a00.z + w01*a01.z + w10*a10.z + w11*a11.z;
            float s3 = w00*a00.w + w01*a01.w + w10*a10.w + w11*a11.w;
            unsigned h0, l0, h1, l1;
            split2(s0, s1, h0, l0);
            split2(s2, s3, h1, l1);
            *(uint2*)(sAhi + px * RPAD + c4 * 2) = make_uint2(h0, h1);
            *(uint2*)(sAlo + px * RPAD + c4 * 2) = make_uint2(l0, l1);
        }
        // ---- weights tap k -> B hi/lo
        {
            const uint4* bh = (const uint4*)(g_Bhi + k * 4096);
            const uint4* bl = (const uint4*)(g_Blo + k * 4096);
#pragma unroll
            for (int j = 0; j < 2; j++) {
                int idx = tid + j * 256;
                int o   = idx >> 3;
                int kc  = idx & 7;
                *(uint4*)(sBhi + o * RPAD + kc * 16) = bh[idx];
                *(uint4*)(sBlo + o * RPAD + kc * 16) = bl[idx];
            }
        }
        __syncthreads();

        // ---- MMA: per k-step, load A/B hi+lo frags once, 3 passes from regs
#pragma unroll
        for (int ks = 0; ks < 4; ks++) {
            int kcol = ks * 16;
            uint32_t ahi[2][4], alo[2][4], bhi[4][2], blo[4][2];
#pragma unroll
            for (int mf = 0; mf < 2; mf++) {
                uint32_t ar = (uint32_t)(wm + mf * 16 + (lane & 15)) * RPAD
                            + (uint32_t)(kcol + (lane >> 4) * 8) * 2;
                ldsm_x4(ahi[mf], AHI + ar);
                ldsm_x4(alo[mf], ALO + ar);
            }
#pragma unroll
            for (int nf = 0; nf < 4; nf++) {
                uint32_t br = (uint32_t)(wn + nf * 8 + (lane & 7)) * RPAD
                            + (uint32_t)(kcol + ((lane >> 3) & 1) * 8) * 2;
                ldsm_x2(bhi[nf], BHI + br);
                ldsm_x2(blo[nf], BLO + br);
            }
#pragma unroll
            for (int mf = 0; mf < 2; mf++)
#pragma unroll
                for (int nf = 0; nf < 4; nf++) {
                    mma_bf16(acc[mf][nf], ahi[mf], bhi[nf]);
                    mma_bf16(acc[mf][nf], ahi[mf], blo[nf]);
                    mma_bf16(acc[mf][nf], alo[mf], bhi[nf]);
                }
        }
        __syncthreads();
    }

    // ---- epilogue: transpose C through smem, store coalesced NCHW rows
    float* Cst = (float*)smem;     // [64 o][132 px]
#pragma unroll
    for (int mf = 0; mf < 2; mf++)
#pragma unroll
        for (int nf = 0; nf < 4; nf++) {
            int row0 = wm + mf * 16 + (lane >> 2);
            int col0 = wn + nf * 8 + (lane & 3) * 2;
            Cst[(col0    ) * 132 + row0    ] = acc[mf][nf][0];
            Cst[(col0 + 1) * 132 + row0    ] = acc[mf][nf][1];
            Cst[(col0    ) * 132 + row0 + 8] = acc[mf][nf][2];
            Cst[(col0 + 1) * 132 + row0 + 8] = acc[mf][nf][3];
        }
    __syncthreads();
    float* ob = out + ((long)b * COUT) * HW + y * W;
#pragma unroll
    for (int j = 0; j < 8; j++) {
        int idx = tid + j * 256;
        int o   = idx >> 5;
        int p4  = (idx & 31) * 4;
        float4 v = *(const float4*)(Cst + o * 132 + p4);
        *(float4*)(ob + (long)o * HW + p4) = v;
    }
}

// ---------------------------------------------------------------------------
extern "C" void kernel_launch(void* const* d_in, const int* in_sizes, int n_in,
                              void* d_out, int out_size) {
    const float* x  = (const float*)d_in[0];
    const float* wp = (const float*)d_in[1];
    const float* bp = (const float*)d_in[2];
    const float* wd = (const float*)d_in[3];
    float* out = (float*)d_out;

    static int smem_set = 0;
    int fused_smem = 64512;
    int off2_smem  = 65088;
    if (!smem_set) {
        cudaFuncSetAttribute(k_fused, cudaFuncAttributeMaxDynamicSharedMemorySize,
                             fused_smem);
        cudaFuncSetAttribute(k_off2, cudaFuncAttributeMaxDynamicSharedMemorySize,
                             off2_smem);
        smem_set = 1;
    }

    k_zero<<<777, 256>>>();
    k_transpose_x<<<dim3(HW / 32, C / 32, B), dim3(32, 8)>>>(x);
    k_wprep<<<(9 * 64 * 64 + 9 * 32 * 64 + 255) / 256, 256>>>(wd, wp);
    k_off2<<<NTILES, 256, off2_smem>>>(bp);
    k_fused<<<NTILES, 256, fused_smem>>>(out);
}

// round 15
// speedup vs baseline: 1.0790x; 1.0790x over previous
#include <cuda_runtime.h>
#include <cuda_bf16.h>
#include <math.h>
#include <stdint.h>

#define B    4
#define C    64
#define H    128
#define W    128
#define COUT 64
#define KK   18
#define CK   576
#define HW   16384
#define PW   131              // padded width/height (y,x in -1..129)
#define PPX  (PW * PW)        // 17161 padded pixels per image
#define NTILES 512            // one tile = one image row (128 px)
#define RPAD 144              // smem row pitch in bytes (72 bf16)

// Scratch (device globals — no runtime allocation allowed)
__device__ float g_xp[B * PPX * C];          // zero-padded NHWC x
__device__ float g_off[B * HW * KK];         // offsets [b][y][x][18]
__device__ __nv_bfloat16 g_Bhi[9 * 64 * 64]; // w_d [tap][o][c] bf16 hi
__device__ __nv_bfloat16 g_Blo[9 * 64 * 64]; // w_d [tap][o][c] bf16 lo
__device__ __nv_bfloat16 g_Phi[9 * 32 * 64]; // w_p [tap][kk(pad32)][c] hi
__device__ __nv_bfloat16 g_Plo[9 * 32 * 64]; // w_p [tap][kk(pad32)][c] lo

// ---------------- warp-MMA helpers (baseline PTX, sm_80+) ----------------
__device__ __forceinline__ uint32_t smem_u32(const void* p) {
    uint32_t a;
    asm("{ .reg .u64 t; cvta.to.shared.u64 t, %1; cvt.u32.u64 %0, t; }"
        : "=r"(a) : "l"(p));
    return a;
}
__device__ __forceinline__ void ldsm_x4(uint32_t* r, uint32_t addr) {
    asm volatile("ldmatrix.sync.aligned.m8n8.x4.shared.b16 {%0,%1,%2,%3}, [%4];"
                 : "=r"(r[0]), "=r"(r[1]), "=r"(r[2]), "=r"(r[3]) : "r"(addr));
}
__device__ __forceinline__ void ldsm_x2(uint32_t* r, uint32_t addr) {
    asm volatile("ldmatrix.sync.aligned.m8n8.x2.shared.b16 {%0,%1}, [%2];"
                 : "=r"(r[0]), "=r"(r[1]) : "r"(addr));
}
__device__ __forceinline__ void mma_bf16(float* c, const uint32_t* a,
                                         const uint32_t* b) {
    asm volatile(
        "mma.sync.aligned.m16n8k16.row.col.f32.bf16.bf16.f32 "
        "{%0,%1,%2,%3}, {%4,%5,%6,%7}, {%8,%9}, {%0,%1,%2,%3};"
        : "+f"(c[0]), "+f"(c[1]), "+f"(c[2]), "+f"(c[3])
        : "r"(a[0]), "r"(a[1]), "r"(a[2]), "r"(a[3]), "r"(b[0]), "r"(b[1]));
}
// split two f32 into packed bf16 hi + packed bf16 lo residual
__device__ __forceinline__ void split2(float s0, float s1,
                                       unsigned& hi, unsigned& lo) {
    unsigned h;
    asm("cvt.rn.bf16x2.f32 %0, %1, %2;" : "=r"(h) : "f"(s1), "f"(s0));
    float f0 = __uint_as_float(h << 16);
    float f1 = __uint_as_float(h & 0xffff0000u);
    unsigned l;
    asm("cvt.rn.bf16x2.f32 %0, %1, %2;" : "=r"(l) : "f"(s1 - f1), "f"(s0 - f0));
    hi = h; lo = l;
}

// ---------------------------------------------------------------------------
// Kernel 0: zero the padded border of g_xp (777 border px per image)
// ---------------------------------------------------------------------------
__global__ void k_zero() {
    int i = blockIdx.x * 256 + threadIdx.x;   // 777*4*64 = 198912 items
    int c = i & 63;
    int t = i >> 6;
    int p = t % 777;
    int b = t / 777;
    int ys, xs;
    if (p < 393) {
        int r = p / 131;
        ys = (r == 0) ? 0 : 128 + r;
        xs = p % 131;
    } else {
        int q = p - 393;
        ys = q / 3 + 1;
        int cc = q % 3;
        xs = (cc == 0) ? 0 : 128 + cc;
    }
    g_xp[((long)b * PPX + ys * PW + xs) * C + c] = 0.f;
}

// ---------------------------------------------------------------------------
// Kernel 1: transpose x (B,C,H,W) -> padded NHWC interior
// ---------------------------------------------------------------------------
__global__ void k_transpose_x(const float* __restrict__ x) {
    __shared__ float tile[32][33];
    int b   = blockIdx.z;
    int c0  = blockIdx.y * 32;
    int hw0 = blockIdx.x * 32;
    int tx = threadIdx.x, ty = threadIdx.y;
#pragma unroll
    for (int j = 0; j < 4; j++)
        tile[ty + j * 8][tx] = x[(b * C + c0 + ty + j * 8) * HW + hw0 + tx];
    __syncthreads();
#pragma unroll
    for (int j = 0; j < 4; j++) {
        int hw = hw0 + ty + j * 8;
        int yy = hw >> 7, xx = hw & 127;
        g_xp[((long)b * PPX + (yy + 1) * PW + xx + 1) * C + c0 + tx]
            = tile[tx][ty + j * 8];
    }
}

// ---------------------------------------------------------------------------
// Kernel 2: weight prep — bf16 hi/lo split for both w_d and w_p
// ---------------------------------------------------------------------------
__global__ void k_wprep(const float* __restrict__ wd,
                        const float* __restrict__ wp) {
    int i = blockIdx.x * 256 + threadIdx.x;
    if (i < 9 * 64 * 64) {
        int c = i & 63, o = (i >> 6) & 63, k = i >> 12;
        float v = wd[o * CK + c * 9 + k];
        __nv_bfloat16 h = __float2bfloat16(v);
        g_Bhi[k * 4096 + o * 64 + c] = h;
        g_Blo[k * 4096 + o * 64 + c] = __float2bfloat16(v - __bfloat162float(h));
    } else if (i < 9 * 64 * 64 + 9 * 32 * 64) {
        int j = i - 9 * 64 * 64;
        int c = j & 63, kk = (j >> 6) & 31, k = j >> 11;
        float v = (kk < 18) ? wp[kk * CK + c * 9 + k] : 0.f;
        __nv_bfloat16 h = __float2bfloat16(v);
        g_Phi[k * 2048 + kk * 64 + c] = h;
        g_Plo[k * 2048 + kk * 64 + c] = __float2bfloat16(v - __bfloat162float(h));
    }
}

// ---------------------------------------------------------------------------
// Kernel 3: offset conv as bf16-split HMMA GEMM, row-shift A sharing,
// n=24 warp layout: warp wid -> m = wid*16 (1 m-frag), n = 0..23 (3 n-frags).
// ---------------------------------------------------------------------------
__global__ void __launch_bounds__(256) k_off2(const float* __restrict__ bp) {
    extern __shared__ char smem[];
    char* sAhi = smem;
    char* sAlo = smem + 18720;
    char* sP   = smem + 37440;          // [tap][hi 4608 | lo 4608]
    uint32_t sb  = smem_u32(smem);
    uint32_t AHI = sb, ALO = sb + 18720, PB = sb + 37440;

    int tid  = threadIdx.x;
    int lane = tid & 31;
    int wid  = tid >> 5;
    int tile = blockIdx.x;
    int b    = tile >> 7;
    int y    = tile & 127;

    int c4  = (tid & 15) * 4;
    int pxg = tid >> 4;
    const float* xbase = g_xp + (long)b * PPX * C + c4;

    int wm = wid * 16;
    float acc[3][4];
#pragma unroll
    for (int j = 0; j < 3; j++)
#pragma unroll
        for (int q = 0; q < 4; q++) acc[j][q] = 0.f;

#pragma unroll 1
    for (int ky = 0; ky < 3; ky++) {
        const float* rowp = xbase + (long)((y + ky) * PW) * C;
        // ---- build Awide: 130 stored-px x 64 ch (hi/lo split)
#pragma unroll
        for (int i = 0; i < 8; i++) {
            int j = pxg + 16 * i;
            float4 v = *(const float4*)(rowp + j * C);
            unsigned h0, l0, h1, l1;
            split2(v.x, v.y, h0, l0);
            split2(v.z, v.w, h1, l1);
            *(uint2*)(sAhi + j * RPAD + c4 * 2) = make_uint2(h0, h1);
            *(uint2*)(sAlo + j * RPAD + c4 * 2) = make_uint2(l0, l1);
        }
        if (tid < 32) {                  // px 128, 129
            int j = 128 + (tid >> 4);
            float4 v = *(const float4*)(rowp + j * C);
            unsigned h0, l0, h1, l1;
            split2(v.x, v.y, h0, l0);
            split2(v.z, v.w, h1, l1);
            *(uint2*)(sAhi + j * RPAD + c4 * 2) = make_uint2(h0, h1);
            *(uint2*)(sAlo + j * RPAD + c4 * 2) = make_uint2(l0, l1);
        }
        // ---- preload this ky's 3 weight tiles (hi+lo)
#pragma unroll
        for (int j = 0; j < 6; j++) {
            int idx  = tid + j * 256;
            int tap  = idx >> 9;
            int r    = idx & 511;
            int half = r >> 8;
            int e    = r & 255;
            int o    = e >> 3, kc = e & 7;
            const uint4* src = half
                ? (const uint4*)(g_Plo + (ky * 3 + tap) * 2048)
                : (const uint4*)(g_Phi + (ky * 3 + tap) * 2048);
            *(uint4*)(sP + tap * 9216 + half * 4608 + o * RPAD + kc * 16)
                = src[e];
        }
        __syncthreads();

        // ---- 3 taps from the shared Awide (base shifted by kx*RPAD)
#pragma unroll
        for (int kx = 0; kx < 3; kx++) {
            uint32_t Abase = (uint32_t)(kx * RPAD);
            uint32_t PHI = PB + kx * 9216, PLO = PHI + 4608;
#pragma unroll
            for (int ks = 0; ks < 4; ks++) {
                int kcol = ks * 16;
                uint32_t ahi[4], alo[4], bhi[3][2], blo[3][2];
                uint32_t ar = Abase
                    + (uint32_t)(wm + (lane & 15)) * RPAD
                    + (uint32_t)(kcol + (lane >> 4) * 8) * 2;
                ldsm_x4(ahi, AHI + ar);
                ldsm_x4(alo, ALO + ar);
#pragma unroll
                for (int nf = 0; nf < 3; nf++) {
                    uint32_t br = (uint32_t)(nf * 8 + (lane & 7)) * RPAD
                                + (uint32_t)(kcol + ((lane >> 3) & 1) * 8) * 2;
                    ldsm_x2(bhi[nf], PHI + br);
                    ldsm_x2(blo[nf], PLO + br);
                }
#pragma unroll
                for (int nf = 0; nf < 3; nf++) {
                    mma_bf16(acc[nf], ahi, bhi[nf]);
                    mma_bf16(acc[nf], ahi, blo[nf]);
                    mma_bf16(acc[nf], alo, bhi[nf]);
                }
            }
        }
        __syncthreads();
    }

    float* Cst = (float*)smem;
#pragma unroll
    for (int nf = 0; nf < 3; nf++) {
        int row0 = wm + (lane >> 2);
        int col0 = nf * 8 + (lane & 3) * 2;
        if (col0 < 18) {
            Cst[(row0    ) * 20 + col0] = acc[nf][0];
            Cst[(row0 + 8) * 20 + col0] = acc[nf][2];
        }
        if (col0 + 1 < 18) {
            Cst[(row0    ) * 20 + col0 + 1] = acc[nf][1];
            Cst[(row0 + 8) * 20 + col0 + 1] = acc[nf][3];
        }
    }
    __syncthreads();
    {
        int px = tid >> 1;
        int g  = tid & 1;
        float* op = g_off + (long)(b * HW + y * W + px) * KK;
#pragma unroll
        for (int j = 0; j < 9; j++) {
            int kk = g * 9 + j;
            op[kk] = Cst[px * 20 + kk] + bp[kk];
        }
    }
}

// ---------------------------------------------------------------------------
// Kernel 4: fused gather + bf16-split warp-MMA GEMM (R13 version: direct
// g_off reads — they are L1-broadcasts; smem preload proved slower).
// ---------------------------------------------------------------------------
__global__ void __launch_bounds__(256, 2) k_fused(float* __restrict__ out) {
    extern __shared__ char smem[];
    char* sAhi = smem;
    char* sAlo = smem + 18432;
    char* sBhi = smem + 36864;
    char* sBlo = smem + 46080;
    uint32_t sb  = smem_u32(smem);
    uint32_t AHI = sb, ALO = sb + 18432, BHI = sb + 36864, BLO = sb + 46080;

    int tid  = threadIdx.x;
    int lane = tid & 31;
    int wid  = tid >> 5;
    int tile = blockIdx.x;
    int b    = tile >> 7;
    int y    = tile & 127;

    int c4  = (tid & 15) * 4;
    int pxg = tid >> 4;
    const float* offrow = g_off + (long)(b * HW + y * W) * KK;
    const float* xbase  = g_xp + (long)b * PPX * C + c4;

    int wm = (wid & 3) * 32;
    int wn = (wid >> 2) * 32;
    float acc[2][4][4];
#pragma unroll
    for (int i = 0; i < 2; i++)
#pragma unroll
        for (int j = 0; j < 4; j++)
#pragma unroll
            for (int q = 0; q < 4; q++) acc[i][j][q] = 0.f;

#pragma unroll 1
    for (int k = 0; k < 9; k++) {
        int ky = k / 3 - 1, kx = k % 3 - 1;
        // ---- gather tap k -> A_hi/A_lo (maskless padded bilinear)
#pragma unroll
        for (int i = 0; i < 8; i++) {
            int px = pxg + 16 * i;
            const float* op = offrow + px * KK;
            float py  = op[2*k]     + (float)(y  + ky);
            float pxx = op[2*k + 1] + (float)(px + kx);
            py  = fminf(fmaxf(py,  -1.f), 128.f);
            pxx = fminf(fmaxf(pxx, -1.f), 128.f);
            float fy = floorf(py), fx = floorf(pxx);
            float wy = py - fy,    wx = pxx - fx;
            int iy = (int)fy + 1;
            int ix = (int)fx + 1;
            int base = (iy * PW + ix) << 6;
            float4 a00 = *(const float4*)(xbase + base);
            float4 a01 = *(const float4*)(xbase + base + 64);
            float4 a10 = *(const float4*)(xbase + base + PW * 64);
            float4 a11 = *(const float4*)(xbase + base + (PW + 1) * 64);
            float w00 = (1.f - wy) * (1.f - wx);
            float w01 = (1.f - wy) * wx;
            float w10 = wy * (1.f - wx);
            float w11 = wy * wx;
            float s0 = w00*a00.x + w01*a01.x + w10*a10.x + w11*a11.x;
            float s1 = w00*a00.y + w01*a01.y + w10*a10.y + w11*a11.y;
            float s2 = w00*a00.z + w01*a01.z + w10*a10.z + w11*a11.z;
            float s3 = w00*a00.w + w01*a01.w + w10*a10.w + w11*a11.w;
            unsigned h0, l0, h1, l1;
            split2(s0, s1, h0, l0);
            split2(s2, s3, h1, l1);
            *(uint2*)(sAhi + px * RPAD + c4 * 2) = make_uint2(h0, h1);
            *(uint2*)(sAlo + px * RPAD + c4 * 2) = make_uint2(l0, l1);
        }
        // ---- weights tap k -> B hi/lo
        {
            const uint4* bh = (const uint4*)(g_Bhi + k * 4096);
            const uint4* bl = (const uint4*)(g_Blo + k * 4096);
#pragma unroll
            for (int j = 0; j < 2; j++) {
                int idx = tid + j * 256;
                int o   = idx >> 3;
                int kc  = idx & 7;
                *(uint4*)(sBhi + o * RPAD + kc * 16) = bh[idx];
                *(uint4*)(sBlo + o * RPAD + kc * 16) = bl[idx];
            }
        }
        __syncthreads();

        // ---- MMA: per k-step, load A/B hi+lo frags once, 3 passes from regs
#pragma unroll
        for (int ks = 0; ks < 4; ks++) {
            int kcol = ks * 16;
            uint32_t ahi[2][4], alo[2][4], bhi[4][2], blo[4][2];
#pragma unroll
            for (int mf = 0; mf < 2; mf++) {
                uint32_t ar = (uint32_t)(wm + mf * 16 + (lane & 15)) * RPAD
                            + (uint32_t)(kcol + (lane >> 4) * 8) * 2;
                ldsm_x4(ahi[mf], AHI + ar);
                ldsm_x4(alo[mf], ALO + ar);
            }
#pragma unroll
            for (int nf = 0; nf < 4; nf++) {
                uint32_t br = (uint32_t)(wn + nf * 8 + (lane & 7)) * RPAD
                            + (uint32_t)(kcol + ((lane >> 3) & 1) * 8) * 2;
                ldsm_x2(bhi[nf], BHI + br);
                ldsm_x2(blo[nf], BLO + br);
            }
#pragma unroll
            for (int mf = 0; mf < 2; mf++)
#pragma unroll
                for (int nf = 0; nf < 4; nf++) {
                    mma_bf16(acc[mf][nf], ahi[mf], bhi[nf]);
                    mma_bf16(acc[mf][nf], ahi[mf], blo[nf]);
                    mma_bf16(acc[mf][nf], alo[mf], bhi[nf]);
                }
        }
        __syncthreads();
    }

    // ---- epilogue: transpose C through smem, store coalesced NCHW rows
    float* Cst = (float*)smem;     // [64 o][132 px]
#pragma unroll
    for (int mf = 0; mf < 2; mf++)
#pragma unroll
        for (int nf = 0; nf < 4; nf++) {
            int row0 = wm + mf * 16 + (lane >> 2);
            int col0 = wn + nf * 8 + (lane & 3) * 2;
            Cst[(col0    ) * 132 + row0    ] = acc[mf][nf][0];
            Cst[(col0 + 1) * 132 + row0    ] = acc[mf][nf][1];
            Cst[(col0    ) * 132 + row0 + 8] = acc[mf][nf][2];
            Cst[(col0 + 1) * 132 + row0 + 8] = acc[mf][nf][3];
        }
    __syncthreads();
    float* ob = out + ((long)b * COUT) * HW + y * W;
#pragma unroll
    for (int j = 0; j < 8; j++) {
        int idx = tid + j * 256;
        int o   = idx >> 5;
        int p4  = (idx & 31) * 4;
        float4 v = *(const float4*)(Cst + o * 132 + p4);
        *(float4*)(ob + (long)o * HW + p4) = v;
    }
}

// ---------------------------------------------------------------------------
extern "C" void kernel_launch(void* const* d_in, const int* in_sizes, int n_in,
                              void* d_out, int out_size) {
    const float* x  = (const float*)d_in[0];
    const float* wp = (const float*)d_in[1];
    const float* bp = (const float*)d_in[2];
    const float* wd = (const float*)d_in[3];
    float* out = (float*)d_out;

    static int smem_set = 0;
    int fused_smem = 55296;
    int off2_smem  = 65088;
    if (!smem_set) {
        cudaFuncSetAttribute(k_fused, cudaFuncAttributeMaxDynamicSharedMemorySize,
                             fused_smem);
        cudaFuncSetAttribute(k_off2, cudaFuncAttributeMaxDynamicSharedMemorySize,
                             off2_smem);
        smem_set = 1;
    }

    k_zero<<<777, 256>>>();
    k_transpose_x<<<dim3(HW / 32, C / 32, B), dim3(32, 8)>>>(x);
    k_wprep<<<(9 * 64 * 64 + 9 * 32 * 64 + 255) / 256, 256>>>(wd, wp);
    k_off2<<<NTILES, 256, off2_smem>>>(bp);
    k_fused<<<NTILES, 256, fused_smem>>>(out);
}

// round 16
// speedup vs baseline: 1.0794x; 1.0003x over previous
#include <cuda_runtime.h>
#include <cuda_bf16.h>
#include <math.h>
#include <stdint.h>

#define B    4
#define C    64
#define H    128
#define W    128
#define COUT 64
#define KK   18
#define CK   576
#define HW   16384
#define PW   131              // padded width/height (y,x in -1..129)
#define PPX  (PW * PW)        // 17161 padded pixels per image
#define NTILES 512            // k_off2: one tile = one image row (128 px)
#define NT2  1024             // k_fused: one tile = 64 px (half row)
#define RPAD 144              // smem row pitch in bytes (72 bf16)

// Scratch (device globals — no runtime allocation allowed)
__device__ float g_xp[B * PPX * C];          // zero-padded NHWC x
__device__ float g_off[B * HW * KK];         // offsets [b][y][x][18]
__device__ __nv_bfloat16 g_Bhi[9 * 64 * 64]; // w_d [tap][o][c] bf16 hi
__device__ __nv_bfloat16 g_Blo[9 * 64 * 64]; // w_d [tap][o][c] bf16 lo
__device__ __nv_bfloat16 g_Phi[9 * 32 * 64]; // w_p [tap][kk(pad32)][c] hi
__device__ __nv_bfloat16 g_Plo[9 * 32 * 64]; // w_p [tap][kk(pad32)][c] lo

// ---------------- warp-MMA helpers (baseline PTX, sm_80+) ----------------
__device__ __forceinline__ uint32_t smem_u32(const void* p) {
    uint32_t a;
    asm("{ .reg .u64 t; cvta.to.shared.u64 t, %1; cvt.u32.u64 %0, t; }"
        : "=r"(a) : "l"(p));
    return a;
}
__device__ __forceinline__ void ldsm_x4(uint32_t* r, uint32_t addr) {
    asm volatile("ldmatrix.sync.aligned.m8n8.x4.shared.b16 {%0,%1,%2,%3}, [%4];"
                 : "=r"(r[0]), "=r"(r[1]), "=r"(r[2]), "=r"(r[3]) : "r"(addr));
}
__device__ __forceinline__ void ldsm_x2(uint32_t* r, uint32_t addr) {
    asm volatile("ldmatrix.sync.aligned.m8n8.x2.shared.b16 {%0,%1}, [%2];"
                 : "=r"(r[0]), "=r"(r[1]) : "r"(addr));
}
__device__ __forceinline__ void mma_bf16(float* c, const uint32_t* a,
                                         const uint32_t* b) {
    asm volatile(
        "mma.sync.aligned.m16n8k16.row.col.f32.bf16.bf16.f32 "
        "{%0,%1,%2,%3}, {%4,%5,%6,%7}, {%8,%9}, {%0,%1,%2,%3};"
        : "+f"(c[0]), "+f"(c[1]), "+f"(c[2]), "+f"(c[3])
        : "r"(a[0]), "r"(a[1]), "r"(a[2]), "r"(a[3]), "r"(b[0]), "r"(b[1]));
}
// split two f32 into packed bf16 hi + packed bf16 lo residual
__device__ __forceinline__ void split2(float s0, float s1,
                                       unsigned& hi, unsigned& lo) {
    unsigned h;
    asm("cvt.rn.bf16x2.f32 %0, %1, %2;" : "=r"(h) : "f"(s1), "f"(s0));
    float f0 = __uint_as_float(h << 16);
    float f1 = __uint_as_float(h & 0xffff0000u);
    unsigned l;
    asm("cvt.rn.bf16x2.f32 %0, %1, %2;" : "=r"(l) : "f"(s1 - f1), "f"(s0 - f0));
    hi = h; lo = l;
}

// ---------------------------------------------------------------------------
// Kernel 0: zero the padded border of g_xp (777 border px per image)
// ---------------------------------------------------------------------------
__global__ void k_zero() {
    int i = blockIdx.x * 256 + threadIdx.x;   // 777*4*64 = 198912 items
    int c = i & 63;
    int t = i >> 6;
    int p = t % 777;
    int b = t / 777;
    int ys, xs;
    if (p < 393) {
        int r = p / 131;
        ys = (r == 0) ? 0 : 128 + r;
        xs = p % 131;
    } else {
        int q = p - 393;
        ys = q / 3 + 1;
        int cc = q % 3;
        xs = (cc == 0) ? 0 : 128 + cc;
    }
    g_xp[((long)b * PPX + ys * PW + xs) * C + c] = 0.f;
}

// ---------------------------------------------------------------------------
// Kernel 1: transpose x (B,C,H,W) -> padded NHWC interior
// ---------------------------------------------------------------------------
__global__ void k_transpose_x(const float* __restrict__ x) {
    __shared__ float tile[32][33];
    int b   = blockIdx.z;
    int c0  = blockIdx.y * 32;
    int hw0 = blockIdx.x * 32;
    int tx = threadIdx.x, ty = threadIdx.y;
#pragma unroll
    for (int j = 0; j < 4; j++)
        tile[ty + j * 8][tx] = x[(b * C + c0 + ty + j * 8) * HW + hw0 + tx];
    __syncthreads();
#pragma unroll
    for (int j = 0; j < 4; j++) {
        int hw = hw0 + ty + j * 8;
        int yy = hw >> 7, xx = hw & 127;
        g_xp[((long)b * PPX + (yy + 1) * PW + xx + 1) * C + c0 + tx]
            = tile[tx][ty + j * 8];
    }
}

// ---------------------------------------------------------------------------
// Kernel 2: weight prep — bf16 hi/lo split for both w_d and w_p
// ---------------------------------------------------------------------------
__global__ void k_wprep(const float* __restrict__ wd,
                        const float* __restrict__ wp) {
    int i = blockIdx.x * 256 + threadIdx.x;
    if (i < 9 * 64 * 64) {
        int c = i & 63, o = (i >> 6) & 63, k = i >> 12;
        float v = wd[o * CK + c * 9 + k];
        __nv_bfloat16 h = __float2bfloat16(v);
        g_Bhi[k * 4096 + o * 64 + c] = h;
        g_Blo[k * 4096 + o * 64 + c] = __float2bfloat16(v - __bfloat162float(h));
    } else if (i < 9 * 64 * 64 + 9 * 32 * 64) {
        int j = i - 9 * 64 * 64;
        int c = j & 63, kk = (j >> 6) & 31, k = j >> 11;
        float v = (kk < 18) ? wp[kk * CK + c * 9 + k] : 0.f;
        __nv_bfloat16 h = __float2bfloat16(v);
        g_Phi[k * 2048 + kk * 64 + c] = h;
        g_Plo[k * 2048 + kk * 64 + c] = __float2bfloat16(v - __bfloat162float(h));
    }
}

// ---------------------------------------------------------------------------
// Kernel 3: offset conv as bf16-split HMMA GEMM, row-shift A sharing,
// n=24 warp layout (unchanged from R14/R15 best).
// ---------------------------------------------------------------------------
__global__ void __launch_bounds__(256) k_off2(const float* __restrict__ bp) {
    extern __shared__ char smem[];
    char* sAhi = smem;
    char* sAlo = smem + 18720;
    char* sP   = smem + 37440;          // [tap][hi 4608 | lo 4608]
    uint32_t sb  = smem_u32(smem);
    uint32_t AHI = sb, ALO = sb + 18720, PB = sb + 37440;

    int tid  = threadIdx.x;
    int lane = tid & 31;
    int wid  = tid >> 5;
    int tile = blockIdx.x;
    int b    = tile >> 7;
    int y    = tile & 127;

    int c4  = (tid & 15) * 4;
    int pxg = tid >> 4;
    const float* xbase = g_xp + (long)b * PPX * C + c4;

    int wm = wid * 16;
    float acc[3][4];
#pragma unroll
    for (int j = 0; j < 3; j++)
#pragma unroll
        for (int q = 0; q < 4; q++) acc[j][q] = 0.f;

#pragma unroll 1
    for (int ky = 0; ky < 3; ky++) {
        const float* rowp = xbase + (long)((y + ky) * PW) * C;
#pragma unroll
        for (int i = 0; i < 8; i++) {
            int j = pxg + 16 * i;
            float4 v = *(const float4*)(rowp + j * C);
            unsigned h0, l0, h1, l1;
            split2(v.x, v.y, h0, l0);
            split2(v.z, v.w, h1, l1);
            *(uint2*)(sAhi + j * RPAD + c4 * 2) = make_uint2(h0, h1);
            *(uint2*)(sAlo + j * RPAD + c4 * 2) = make_uint2(l0, l1);
        }
        if (tid < 32) {                  // px 128, 129
            int j = 128 + (tid >> 4);
            float4 v = *(const float4*)(rowp + j * C);
            unsigned h0, l0, h1, l1;
            split2(v.x, v.y, h0, l0);
            split2(v.z, v.w, h1, l1);
            *(uint2*)(sAhi + j * RPAD + c4 * 2) = make_uint2(h0, h1);
            *(uint2*)(sAlo + j * RPAD + c4 * 2) = make_uint2(l0, l1);
        }
#pragma unroll
        for (int j = 0; j < 6; j++) {
            int idx  = tid + j * 256;
            int tap  = idx >> 9;
            int r    = idx & 511;
            int half = r >> 8;
            int e    = r & 255;
            int o    = e >> 3, kc = e & 7;
            const uint4* src = half
                ? (const uint4*)(g_Plo + (ky * 3 + tap) * 2048)
                : (const uint4*)(g_Phi + (ky * 3 + tap) * 2048);
            *(uint4*)(sP + tap * 9216 + half * 4608 + o * RPAD + kc * 16)
                = src[e];
        }
        __syncthreads();

#pragma unroll
        for (int kx = 0; kx < 3; kx++) {
            uint32_t Abase = (uint32_t)(kx * RPAD);
            uint32_t PHI = PB + kx * 9216, PLO = PHI + 4608;
#pragma unroll
            for (int ks = 0; ks < 4; ks++) {
                int kcol = ks * 16;
                uint32_t ahi[4], alo[4], bhi[3][2], blo[3][2];
                uint32_t ar = Abase
                    + (uint32_t)(wm + (lane & 15)) * RPAD
                    + (uint32_t)(kcol + (lane >> 4) * 8) * 2;
                ldsm_x4(ahi, AHI + ar);
                ldsm_x4(alo, ALO + ar);
#pragma unroll
                for (int nf = 0; nf < 3; nf++) {
                    uint32_t br = (uint32_t)(nf * 8 + (lane & 7)) * RPAD
                                + (uint32_t)(kcol + ((lane >> 3) & 1) * 8) * 2;
                    ldsm_x2(bhi[nf], PHI + br);
                    ldsm_x2(blo[nf], PLO + br);
                }
#pragma unroll
                for (int nf = 0; nf < 3; nf++) {
                    mma_bf16(acc[nf], ahi, bhi[nf]);
                    mma_bf16(acc[nf], ahi, blo[nf]);
                    mma_bf16(acc[nf], alo, bhi[nf]);
                }
            }
        }
        __syncthreads();
    }

    float* Cst = (float*)smem;
#pragma unroll
    for (int nf = 0; nf < 3; nf++) {
        int row0 = wm + (lane >> 2);
        int col0 = nf * 8 + (lane & 3) * 2;
        if (col0 < 18) {
            Cst[(row0    ) * 20 + col0] = acc[nf][0];
            Cst[(row0 + 8) * 20 + col0] = acc[nf][2];
        }
        if (col0 + 1 < 18) {
            Cst[(row0    ) * 20 + col0 + 1] = acc[nf][1];
            Cst[(row0 + 8) * 20 + col0 + 1] = acc[nf][3];
        }
    }
    __syncthreads();
    {
        int px = tid >> 1;
        int g  = tid & 1;
        float* op = g_off + (long)(b * HW + y * W + px) * KK;
#pragma unroll
        for (int j = 0; j < 9; j++) {
            int kk = g * 9 + j;
            op[kk] = Cst[px * 20 + kk] + bp[kk];
        }
    }
}

// ---------------------------------------------------------------------------
// Kernel 4: fused gather + bf16-split warp-MMA GEMM. 64 px x 64 out per
// block (1024 blocks), 8 warps as 2m x 4n (32px x 16o each), acc = 16 regs,
// smem 36.9 KB, __launch_bounds__(256,3) -> 3 blocks/SM, 24 warps.
// ---------------------------------------------------------------------------
__global__ void __launch_bounds__(256, 3) k_fused(float* __restrict__ out) {
    extern __shared__ char smem[];
    char* sAhi = smem;                  //  64 x RPAD = 9216
    char* sAlo = smem + 9216;
    char* sBhi = smem + 18432;          //  64 x RPAD = 9216
    char* sBlo = smem + 27648;
    uint32_t sb  = smem_u32(smem);
    uint32_t AHI = sb, ALO = sb + 9216, BHI = sb + 18432, BLO = sb + 27648;

    int tid  = threadIdx.x;
    int lane = tid & 31;
    int wid  = tid >> 5;
    int tile = blockIdx.x;              // ((b*128)+y)*2 + half
    int half = tile & 1;
    int row  = tile >> 1;
    int b    = row >> 7;
    int y    = row & 127;
    int xh   = half * 64;

    int c4  = (tid & 15) * 4;
    int pxg = tid >> 4;                 // 0..15
    const float* offrow = g_off + (long)(b * HW + y * W + xh) * KK;
    const float* xbase  = g_xp + (long)b * PPX * C + c4;

    int wm = (wid & 1) * 32;
    int wn = (wid >> 1) * 16;
    float acc[2][2][4];
#pragma unroll
    for (int i = 0; i < 2; i++)
#pragma unroll
        for (int j = 0; j < 2; j++)
#pragma unroll
            for (int q = 0; q < 4; q++) acc[i][j][q] = 0.f;

#pragma unroll 1
    for (int k = 0; k < 9; k++) {
        int ky = k / 3 - 1, kx = k % 3 - 1;
        // ---- gather tap k -> A_hi/A_lo (maskless padded bilinear)
#pragma unroll
        for (int i = 0; i < 4; i++) {
            int px = pxg + 16 * i;      // local 0..63
            const float* op = offrow + px * KK;
            float py  = op[2*k]     + (float)(y  + ky);
            float pxx = op[2*k + 1] + (float)(xh + px + kx);
            py  = fminf(fmaxf(py,  -1.f), 128.f);
            pxx = fminf(fmaxf(pxx, -1.f), 128.f);
            float fy = floorf(py), fx = floorf(pxx);
            float wy = py - fy,    wx = pxx - fx;
            int iy = (int)fy + 1;
            int ix = (int)fx + 1;
            int base = (iy * PW + ix) << 6;
            float4 a00 = *(const float4*)(xbase + base);
            float4 a01 = *(const float4*)(xbase + base + 64);
            float4 a10 = *(const float4*)(xbase + base + PW * 64);
            float4 a11 = *(const float4*)(xbase + base + (PW + 1) * 64);
            float w00 = (1.f - wy) * (1.f - wx);
            float w01 = (1.f - wy) * wx;
            float w10 = wy * (1.f - wx);
            float w11 = wy * wx;
            float s0 = w00*a00.x + w01*a01.x + w10*a10.x + w11*a11.x;
            float s1 = w00*a00.y + w01*a01.y + w10*a10.y + w11*a11.y;
            float s2 = w00*a00.z + w01*a01.z + w10*a10.z + w11*a11.z;
            float s3 = w00*a00.w + w01*a01.w + w10*a10.w + w11*a11.w;
            unsigned h0, l0, h1, l1;
            split2(s0, s1, h0, l0);
            split2(s2, s3, h1, l1);
            *(uint2*)(sAhi + px * RPAD + c4 * 2) = make_uint2(h0, h1);
            *(uint2*)(sAlo + px * RPAD + c4 * 2) = make_uint2(l0, l1);
        }
        // ---- weights tap k -> B hi/lo
        {
            const uint4* bh = (const uint4*)(g_Bhi + k * 4096);
            const uint4* bl = (const uint4*)(g_Blo + k * 4096);
#pragma unroll
            for (int j = 0; j < 2; j++) {
                int idx = tid + j * 256;
                int o   = idx >> 3;
                int kc  = idx & 7;
                *(uint4*)(sBhi + o * RPAD + kc * 16) = bh[idx];
                *(uint4*)(sBlo + o * RPAD + kc * 16) = bl[idx];
            }
        }
        __syncthreads();

        // ---- MMA: per k-step, load A/B hi+lo frags once, 3 passes from regs
#pragma unroll
        for (int ks = 0; ks < 4; ks++) {
            int kcol = ks * 16;
            uint32_t ahi[2][4], alo[2][4], bhi[2][2], blo[2][2];
#pragma unroll
            for (int mf = 0; mf < 2; mf++) {
                uint32_t ar = (uint32_t)(wm + mf * 16 + (lane & 15)) * RPAD
                            + (uint32_t)(kcol + (lane >> 4) * 8) * 2;
                ldsm_x4(ahi[mf], AHI + ar);
                ldsm_x4(alo[mf], ALO + ar);
            }
#pragma unroll
            for (int nf = 0; nf < 2; nf++) {
                uint32_t br = (uint32_t)(wn + nf * 8 + (lane & 7)) * RPAD
                            + (uint32_t)(kcol + ((lane >> 3) & 1) * 8) * 2;
                ldsm_x2(bhi[nf], BHI + br);
                ldsm_x2(blo[nf], BLO + br);
            }
#pragma unroll
            for (int mf = 0; mf < 2; mf++)
#pragma unroll
                for (int nf = 0; nf < 2; nf++) {
                    mma_bf16(acc[mf][nf], ahi[mf], bhi[nf]);
                    mma_bf16(acc[mf][nf], ahi[mf], blo[nf]);
                    mma_bf16(acc[mf][nf], alo[mf], bhi[nf]);
                }
        }
        __syncthreads();
    }

    // ---- epilogue: transpose C through smem, store coalesced NCHW rows
    float* Cst = (float*)smem;     // [64 o][68 px]
#pragma unroll
    for (int mf = 0; mf < 2; mf++)
#pragma unroll
        for (int nf = 0; nf < 2; nf++) {
            int row0 = wm + mf * 16 + (lane >> 2);
            int col0 = wn + nf * 8 + (lane & 3) * 2;
            Cst[(col0    ) * 68 + row0    ] = acc[mf][nf][0];
            Cst[(col0 + 1) * 68 + row0    ] = acc[mf][nf][1];
            Cst[(col0    ) * 68 + row0 + 8] = acc[mf][nf][2];
            Cst[(col0 + 1) * 68 + row0 + 8] = acc[mf][nf][3];
        }
    __syncthreads();
    float* ob = out + ((long)b * COUT) * HW + y * W + xh;
#pragma unroll
    for (int j = 0; j < 4; j++) {
        int idx = tid + j * 256;       // 1024 float4 chunks
        int o   = idx >> 4;
        int p4  = (idx & 15) * 4;
        float4 v = *(const float4*)(Cst + o * 68 + p4);
        *(float4*)(ob + (long)o * HW + p4) = v;
    }
}

// ---------------------------------------------------------------------------
extern "C" void kernel_launch(void* const* d_in, const int* in_sizes, int n_in,
                              void* d_out, int out_size) {
    const float* x  = (const float*)d_in[0];
    const float* wp = (const float*)d_in[1];
    const float* bp = (const float*)d_in[2];
    const float* wd = (const float*)d_in[3];
    float* out = (float*)d_out;

    static int smem_set = 0;
    int fused_smem = 36864;
    int off2_smem  = 65088;
    if (!smem_set) {
        cudaFuncSetAttribute(k_fused, cudaFuncAttributeMaxDynamicSharedMemorySize,
                             fused_smem);
        cudaFuncSetAttribute(k_off2, cudaFuncAttributeMaxDynamicSharedMemorySize,
                             off2_smem);
        smem_set = 1;
    }

    k_zero<<<777, 256>>>();
    k_transpose_x<<<dim3(HW / 32, C / 32, B), dim3(32, 8)>>>(x);
    k_wprep<<<(9 * 64 * 64 + 9 * 32 * 64 + 255) / 256, 256>>>(wd, wp);
    k_off2<<<NTILES, 256, off2_smem>>>(bp);
    k_fused<<<NT2, 256, fused_smem>>>(out);
}